// round 1
// baseline (speedup 1.0000x reference)
#include <cuda_runtime.h>
#include <math.h>

// ============================================================================
// MoEGate (DeepSeek-V3 router) for GB300
//   logits[T,256] = hidden[T,7168] @ weight[256,7168]^T      (fp32 GEMM)
//   scores = sigmoid(logits); sc = scores + bias
//   group(8 x 32) top-2 sums -> top-4 groups -> mask -> top-8 experts
//   weights = scores[topk] / (sum + 1e-20) * 2.5
// Output layout (float32): [ topk_idx (T*8 floats) ; topk_weight (T*8 floats) ]
// ============================================================================

#define N_EXPERTS 256
#define N_GROUP 8
#define EPG 32            // experts per group
#define TOP_K 8
#define TOPK_GROUP 4
#define MAX_T 8192

__device__ float g_logits[MAX_T * N_EXPERTS];

// ---------------------------------------------------------------------------
// GEMM: C[t][e] = sum_h A[t][h] * B[e][h]   (both K-major, K = 7168)
// BM=64, BN=64, BK=16, 256 threads, 4x4 micro-tile per thread.
// ---------------------------------------------------------------------------
#define BM 64
#define BN 64
#define BK 16
#define SPAD 68   // padded row (floats), 68*4 = 272 bytes (16B multiple)

__global__ void __launch_bounds__(256)
gemm_kernel(const float* __restrict__ A, const float* __restrict__ B,
            int T, int K)
{
    __shared__ float As[BK][SPAD];
    __shared__ float Bs[BK][SPAD];

    const int tid = threadIdx.x;
    const int tx = tid % 16;          // output column group
    const int ty = tid / 16;          // output row group
    const int bm = blockIdx.y * BM;   // token base
    const int bn = blockIdx.x * BN;   // expert base

    // cooperative load indices: each thread loads one float4 of A and one of B
    const int lr = tid >> 2;            // 0..63 row within tile
    const int lc = (tid & 3) << 2;      // 0,4,8,12 k-offset within tile

    const float* Ab = A + (size_t)(bm + lr) * K + lc;
    const float* Bb = B + (size_t)(bn + lr) * K + lc;

    float acc[4][4];
#pragma unroll
    for (int i = 0; i < 4; i++)
#pragma unroll
        for (int j = 0; j < 4; j++) acc[i][j] = 0.0f;

    for (int k0 = 0; k0 < K; k0 += BK) {
        float4 a4 = *(const float4*)(Ab + k0);
        float4 b4 = *(const float4*)(Bb + k0);
        As[lc + 0][lr] = a4.x; As[lc + 1][lr] = a4.y;
        As[lc + 2][lr] = a4.z; As[lc + 3][lr] = a4.w;
        Bs[lc + 0][lr] = b4.x; Bs[lc + 1][lr] = b4.y;
        Bs[lc + 2][lr] = b4.z; Bs[lc + 3][lr] = b4.w;
        __syncthreads();

#pragma unroll
        for (int kk = 0; kk < BK; kk++) {
            float4 av = *(const float4*)(&As[kk][ty << 2]);
            float4 bv = *(const float4*)(&Bs[kk][tx << 2]);
            float a[4] = {av.x, av.y, av.z, av.w};
            float b[4] = {bv.x, bv.y, bv.z, bv.w};
#pragma unroll
            for (int i = 0; i < 4; i++)
#pragma unroll
                for (int j = 0; j < 4; j++)
                    acc[i][j] = fmaf(a[i], b[j], acc[i][j]);
        }
        __syncthreads();
    }

    // write logits
#pragma unroll
    for (int i = 0; i < 4; i++) {
        int t = bm + (ty << 2) + i;
        float* Crow = g_logits + (size_t)t * N_EXPERTS + bn + (tx << 2);
#pragma unroll
        for (int j = 0; j < 4; j++) Crow[j] = acc[i][j];
    }
}

// ---------------------------------------------------------------------------
// Gating: one warp per token. 8 warps (8 tokens) per block.
// ---------------------------------------------------------------------------
__device__ __forceinline__ void argmax_red(float& v, int& i)
{
#pragma unroll
    for (int o = 16; o > 0; o >>= 1) {
        float v2 = __shfl_down_sync(0xffffffffu, v, o);
        int   i2 = __shfl_down_sync(0xffffffffu, i, o);
        if (v2 > v || (v2 == v && i2 < i)) { v = v2; i = i2; }
    }
    v = __shfl_sync(0xffffffffu, v, 0);
    i = __shfl_sync(0xffffffffu, i, 0);
}

__global__ void __launch_bounds__(256)
gate_kernel(const float* __restrict__ bias, float* __restrict__ out,
            int T, int out_size)
{
    __shared__ float ss[8][N_EXPERTS];   // unbiased scores per token
    __shared__ float bs[N_EXPERTS];

    const int tid  = threadIdx.x;
    const int warp = tid >> 5;
    const int lane = tid & 31;
    const int t = blockIdx.x * 8 + warp;

    if (tid < N_EXPERTS) bs[tid] = bias[tid];

    float* s = ss[warp];
    if (t < T) {
        const float* lg = g_logits + (size_t)t * N_EXPERTS;
#pragma unroll
        for (int j = 0; j < 8; j++) {
            int e = j * 32 + lane;
            float x = lg[e];
            s[e] = 1.0f / (1.0f + expf(-x));   // sigmoid
        }
    }
    __syncthreads();
    if (t >= T) return;

    // ---- group scores: sum of top-2 biased scores in each group of 32 ----
    float gsum_mine = 0.0f;   // lane g (g<8) ends up holding group g's sum
#pragma unroll
    for (int g = 0; g < N_GROUP; g++) {
        int e = g * EPG + lane;
        float v = s[e] + bs[e];
        float v1 = v; int i1 = lane;
        argmax_red(v1, i1);
        float v2 = (lane == i1) ? -INFINITY : v;
        int   i2 = lane;
        argmax_red(v2, i2);
        if (lane == g) gsum_mine = v1 + v2;
    }

    // ---- select top-4 groups (tie -> lower group index) ----
    float gv[N_GROUP];
#pragma unroll
    for (int j = 0; j < N_GROUP; j++)
        gv[j] = __shfl_sync(0xffffffffu, gsum_mine, j);

    unsigned gmask = 0;
#pragma unroll
    for (int r = 0; r < TOPK_GROUP; r++) {
        float best = -INFINITY; int bi = 0;
#pragma unroll
        for (int j = 0; j < N_GROUP; j++) {
            if (!((gmask >> j) & 1u) && gv[j] > best) { best = gv[j]; bi = j; }
        }
        gmask |= 1u << bi;
    }

    // ---- top-8 experts among selected groups (by biased score) ----
    // lane owns experts [lane*8, lane*8+8), all in group lane/4
    const bool gok = (gmask >> (lane >> 2)) & 1u;
    unsigned sel = 0;
    int   out_e = 0;
    float out_w = 0.0f;

#pragma unroll
    for (int r = 0; r < TOP_K; r++) {
        float v = -INFINITY; int ie = N_EXPERTS;  // large index so valid wins
        if (gok) {
#pragma unroll
            for (int j = 0; j < 8; j++) {
                if (!((sel >> j) & 1u)) {
                    int e = lane * 8 + j;
                    float val = s[e] + bs[e];
                    if (val > v) { v = val; ie = e; }  // > keeps lowest index
                }
            }
        }
        argmax_red(v, ie);
        if ((ie >> 3) == lane) sel |= 1u << (ie & 7);  // owner marks selection
        if (lane == r) { out_e = ie; out_w = s[ie]; }  // unbiased score
    }

    // ---- normalize: w / (sum + 1e-20) * 2.5 ----
    float wsum = (lane < TOP_K) ? out_w : 0.0f;
#pragma unroll
    for (int o = 16; o > 0; o >>= 1)
        wsum += __shfl_down_sync(0xffffffffu, wsum, o);
    wsum = __shfl_sync(0xffffffffu, wsum, 0);

    if (lane < TOP_K) {
        float denom = wsum + 1e-20f;
        float wn = out_w / denom * 2.5f;
        if (out_size >= 2 * T * TOP_K) {
            out[(size_t)t * TOP_K + lane] = (float)out_e;
            out[(size_t)T * TOP_K + (size_t)t * TOP_K + lane] = wn;
        } else {
            out[(size_t)t * TOP_K + lane] = wn;  // fallback: weights only
        }
    }
}

// ---------------------------------------------------------------------------
extern "C" void kernel_launch(void* const* d_in, const int* in_sizes, int n_in,
                              void* d_out, int out_size)
{
    const float* hidden = (const float*)d_in[0];
    const float* weight = (const float*)d_in[1];
    const float* bias   = (const float*)d_in[2];
    float* out = (float*)d_out;

    const int H = in_sizes[1] / N_EXPERTS;   // 7168
    const int T = in_sizes[0] / H;           // 8192

    dim3 ggrid(N_EXPERTS / BN, (T + BM - 1) / BM);
    gemm_kernel<<<ggrid, 256>>>(hidden, weight, T, H);

    int nblk = (T + 7) / 8;
    gate_kernel<<<nblk, 256>>>(bias, out, T, out_size);
}

// round 5
// speedup vs baseline: 2.3189x; 2.3189x over previous
#include <cuda_runtime.h>
#include <cuda_fp16.h>
#include <math.h>
#include <stdint.h>

// ============================================================================
// MoEGate (DeepSeek-V3 router) for GB300 — round 5
//   logits[T,256] = hidden[T,7168] @ weight[256,7168]^T
//   GEMM: mma.sync fp16 split (hi/lo, 3 products), fp32 accumulation.
//   Precision fixes vs round 4:
//     (1) weights scaled x512 before split (residuals exit fp16 denormal range;
//         unscale x2^-9 exactly in epilogue)
//     (2) two-level accumulators (fold every 8 K-chunks) to shorten the fp32
//         rounding chain: noise ~2.1e-6 -> ~4.5e-7
// Output (float32): [ topk_idx (T*8) ; topk_weight (T*8) ]
// ============================================================================

#define N_EXPERTS 256
#define N_GROUP 8
#define EPG 32
#define TOP_K 8
#define TOPK_GROUP 4
#define MAX_T 8192
#define KDIM 7168

#define WSCALE 512.0f
#define WUNSCALE 0.001953125f   // 1/512, exact

__device__ float g_logits[MAX_T * N_EXPERTS];

// ---------------------------------------------------------------------------
// GEMM: BM=128 x BN=128 per CTA, KC=32 fp32 per chunk, 16 warps (512 thr),
// warp tile 32x32 (4x4 warp grid). smem rows padded to 72B.
// ---------------------------------------------------------------------------
#define BM 128
#define BN 128
#define KC 32
#define NCHUNK (KDIM / KC)          // 224
#define RSTRIDE 72
#define TILE_B (128 * RSTRIDE)      // 9216 B
#define STAGE_B (4 * TILE_B)        // 36864 B
#define DSMEM_REQ (2 * STAGE_B)     // 73728 B

__device__ __forceinline__ void mma_f16(float* c, const uint32_t* a,
                                        const uint32_t* b) {
    asm volatile(
        "mma.sync.aligned.m16n8k16.row.col.f32.f16.f16.f32 "
        "{%0,%1,%2,%3}, {%4,%5,%6,%7}, {%8,%9}, {%0,%1,%2,%3};"
        : "+f"(c[0]), "+f"(c[1]), "+f"(c[2]), "+f"(c[3])
        : "r"(a[0]), "r"(a[1]), "r"(a[2]), "r"(a[3]), "r"(b[0]), "r"(b[1]));
}

__device__ __forceinline__ uint32_t pack_hi(float x, float y) {
    __half2 h(__float2half_rn(x), __float2half_rn(y));
    return *(uint32_t*)&h;
}
__device__ __forceinline__ uint32_t pack_lo(float x, float y) {
    float hx = __half2float(__float2half_rn(x));
    float hy = __half2float(__float2half_rn(y));
    __half2 l(__float2half_rn(x - hx), __float2half_rn(y - hy));
    return *(uint32_t*)&l;
}

__device__ __forceinline__ void cvt_store(char* hi, char* lo, uint32_t off,
                                          float4 v) {
    *(uint2*)(hi + off) = make_uint2(pack_hi(v.x, v.y), pack_hi(v.z, v.w));
    *(uint2*)(lo + off) = make_uint2(pack_lo(v.x, v.y), pack_lo(v.z, v.w));
}

__global__ void __launch_bounds__(512, 1)
gemm_mma_kernel(const float* __restrict__ A, const float* __restrict__ B, int T)
{
    extern __shared__ char smem[];

    const int tid  = threadIdx.x;
    const int wid  = tid >> 5;
    const int lane = tid & 31;
    const int bn = blockIdx.x * BN;
    const int bm = blockIdx.y * BM;

    const int wm = wid >> 2;           // 0..3 -> row offset 32*wm
    const int wn = wid & 3;            // 0..3 -> col offset 32*wn
    const int lg = lane >> 2;          // 0..7
    const int tg = lane & 3;           // 0..3

    // loader: row = tid>>2 (0..127), quarter q = tid&3 -> k offset q*8 floats
    const int lrow = tid >> 2;
    const int lq   = tid & 3;
    const float* Ag = A + (size_t)(bm + lrow) * KDIM + lq * 8;
    const float* Bg = B + (size_t)(bn + lrow) * KDIM + lq * 8;
    const uint32_t sto = (uint32_t)(lrow * RSTRIDE + lq * 16);  // fp16 bytes

    // dual-level accumulators: [mt][nt][4]
    float accH[2][4][4], accL[2][4][4];
#pragma unroll
    for (int i = 0; i < 2; i++)
#pragma unroll
        for (int j = 0; j < 4; j++)
#pragma unroll
            for (int q = 0; q < 4; q++) { accH[i][j][q] = 0.0f; accL[i][j][q] = 0.0f; }

    // ---- prologue: chunk 0 -> stage 0 ----
    {
        char* sAhi = smem;             char* sAlo = smem + TILE_B;
        char* sBhi = smem + 2*TILE_B;  char* sBlo = smem + 3*TILE_B;
#pragma unroll
        for (int j = 0; j < 2; j++) {
            float4 a4 = *(const float4*)(Ag + j * 4);
            float4 b4 = *(const float4*)(Bg + j * 4);
            b4.x *= WSCALE; b4.y *= WSCALE; b4.z *= WSCALE; b4.w *= WSCALE;
            cvt_store(sAhi, sAlo, sto + j * 8, a4);
            cvt_store(sBhi, sBlo, sto + j * 8, b4);
        }
    }
    __syncthreads();

    for (int i = 0; i < NCHUNK; i++) {
        const int b = i & 1;
        char* st = smem + b * STAGE_B;
        char* sAhi = st;               char* sAlo = st + TILE_B;
        char* sBhi = st + 2 * TILE_B;  char* sBlo = st + 3 * TILE_B;

        // prefetch next chunk into registers
        float4 ar[2], br[2];
        const bool more = (i + 1 < NCHUNK);
        if (more) {
            const size_t k0 = (size_t)(i + 1) * KC;
#pragma unroll
            for (int j = 0; j < 2; j++) ar[j] = *(const float4*)(Ag + k0 + j * 4);
#pragma unroll
            for (int j = 0; j < 2; j++) br[j] = *(const float4*)(Bg + k0 + j * 4);
        }

        // compute: 2 k-steps x 3 products x 8 mma
#pragma unroll
        for (int ks = 0; ks < 2; ks++) {
            const uint32_t kb = ks * 32;
            uint32_t afr[2][4], bhi[4][2], blo[4][2];

#pragma unroll
            for (int mt = 0; mt < 2; mt++) {
                uint32_t o = (uint32_t)((wm * 32 + mt * 16 + lg) * RSTRIDE) + kb + tg * 4;
                afr[mt][0] = *(const uint32_t*)(sAhi + o);
                afr[mt][1] = *(const uint32_t*)(sAhi + o + 8 * RSTRIDE);
                afr[mt][2] = *(const uint32_t*)(sAhi + o + 16);
                afr[mt][3] = *(const uint32_t*)(sAhi + o + 8 * RSTRIDE + 16);
            }
#pragma unroll
            for (int nt = 0; nt < 4; nt++) {
                uint32_t o = (uint32_t)((wn * 32 + nt * 8 + lg) * RSTRIDE) + kb + tg * 4;
                bhi[nt][0] = *(const uint32_t*)(sBhi + o);
                bhi[nt][1] = *(const uint32_t*)(sBhi + o + 16);
            }
#pragma unroll
            for (int mt = 0; mt < 2; mt++)
#pragma unroll
                for (int nt = 0; nt < 4; nt++)
                    mma_f16(accL[mt][nt], afr[mt], bhi[nt]);

#pragma unroll
            for (int nt = 0; nt < 4; nt++) {
                uint32_t o = (uint32_t)((wn * 32 + nt * 8 + lg) * RSTRIDE) + kb + tg * 4;
                blo[nt][0] = *(const uint32_t*)(sBlo + o);
                blo[nt][1] = *(const uint32_t*)(sBlo + o + 16);
            }
#pragma unroll
            for (int mt = 0; mt < 2; mt++)
#pragma unroll
                for (int nt = 0; nt < 4; nt++)
                    mma_f16(accL[mt][nt], afr[mt], blo[nt]);

#pragma unroll
            for (int mt = 0; mt < 2; mt++) {
                uint32_t o = (uint32_t)((wm * 32 + mt * 16 + lg) * RSTRIDE) + kb + tg * 4;
                afr[mt][0] = *(const uint32_t*)(sAlo + o);
                afr[mt][1] = *(const uint32_t*)(sAlo + o + 8 * RSTRIDE);
                afr[mt][2] = *(const uint32_t*)(sAlo + o + 16);
                afr[mt][3] = *(const uint32_t*)(sAlo + o + 8 * RSTRIDE + 16);
            }
#pragma unroll
            for (int mt = 0; mt < 2; mt++)
#pragma unroll
                for (int nt = 0; nt < 4; nt++)
                    mma_f16(accL[mt][nt], afr[mt], bhi[nt]);
        }

        // fold local -> main every 8 chunks (224 % 8 == 0: last fold at i=223)
        if ((i & 7) == 7) {
#pragma unroll
            for (int mt = 0; mt < 2; mt++)
#pragma unroll
                for (int nt = 0; nt < 4; nt++)
#pragma unroll
                    for (int q = 0; q < 4; q++) {
                        accH[mt][nt][q] += accL[mt][nt][q];
                        accL[mt][nt][q] = 0.0f;
                    }
        }

        // convert + store next chunk into other stage
        if (more) {
            char* nst = smem + (b ^ 1) * STAGE_B;
            char* nAhi = nst;               char* nAlo = nst + TILE_B;
            char* nBhi = nst + 2 * TILE_B;  char* nBlo = nst + 3 * TILE_B;
#pragma unroll
            for (int j = 0; j < 2; j++) {
                br[j].x *= WSCALE; br[j].y *= WSCALE;
                br[j].z *= WSCALE; br[j].w *= WSCALE;
                cvt_store(nAhi, nAlo, sto + j * 8, ar[j]);
                cvt_store(nBhi, nBlo, sto + j * 8, br[j]);
            }
        }
        __syncthreads();
    }

    // ---- epilogue: unscale by 1/512 and write logits ----
#pragma unroll
    for (int mt = 0; mt < 2; mt++) {
#pragma unroll
        for (int nt = 0; nt < 4; nt++) {
            int row0 = bm + wm * 32 + mt * 16 + lg;
            int col  = bn + wn * 32 + nt * 8 + tg * 2;
            float* d0 = g_logits + (size_t)row0 * N_EXPERTS + col;
            float* d1 = g_logits + (size_t)(row0 + 8) * N_EXPERTS + col;
            *(float2*)d0 = make_float2(accH[mt][nt][0] * WUNSCALE,
                                       accH[mt][nt][1] * WUNSCALE);
            *(float2*)d1 = make_float2(accH[mt][nt][2] * WUNSCALE,
                                       accH[mt][nt][3] * WUNSCALE);
        }
    }
}

// ---------------------------------------------------------------------------
// Gating: one warp per token (verified correct in round 1).
// ---------------------------------------------------------------------------
__device__ __forceinline__ void argmax_red(float& v, int& i)
{
#pragma unroll
    for (int o = 16; o > 0; o >>= 1) {
        float v2 = __shfl_down_sync(0xffffffffu, v, o);
        int   i2 = __shfl_down_sync(0xffffffffu, i, o);
        if (v2 > v || (v2 == v && i2 < i)) { v = v2; i = i2; }
    }
    v = __shfl_sync(0xffffffffu, v, 0);
    i = __shfl_sync(0xffffffffu, i, 0);
}

__global__ void __launch_bounds__(256)
gate_kernel(const float* __restrict__ bias, float* __restrict__ out,
            int T, int out_size)
{
    __shared__ float ss[8][N_EXPERTS];
    __shared__ float bs[N_EXPERTS];

    const int tid  = threadIdx.x;
    const int warp = tid >> 5;
    const int lane = tid & 31;
    const int t = blockIdx.x * 8 + warp;

    if (tid < N_EXPERTS) bs[tid] = bias[tid];

    float* s = ss[warp];
    if (t < T) {
        const float* lg = g_logits + (size_t)t * N_EXPERTS;
#pragma unroll
        for (int j = 0; j < 8; j++) {
            int e = j * 32 + lane;
            float x = lg[e];
            s[e] = 1.0f / (1.0f + expf(-x));
        }
    }
    __syncthreads();
    if (t >= T) return;

    float gsum_mine = 0.0f;
#pragma unroll
    for (int g = 0; g < N_GROUP; g++) {
        int e = g * EPG + lane;
        float v = s[e] + bs[e];
        float v1 = v; int i1 = lane;
        argmax_red(v1, i1);
        float v2 = (lane == i1) ? -INFINITY : v;
        int   i2 = lane;
        argmax_red(v2, i2);
        if (lane == g) gsum_mine = v1 + v2;
    }

    float gv[N_GROUP];
#pragma unroll
    for (int j = 0; j < N_GROUP; j++)
        gv[j] = __shfl_sync(0xffffffffu, gsum_mine, j);

    unsigned gmask = 0;
#pragma unroll
    for (int r = 0; r < TOPK_GROUP; r++) {
        float best = -INFINITY; int bi = 0;
#pragma unroll
        for (int j = 0; j < N_GROUP; j++) {
            if (!((gmask >> j) & 1u) && gv[j] > best) { best = gv[j]; bi = j; }
        }
        gmask |= 1u << bi;
    }

    const bool gok = (gmask >> (lane >> 2)) & 1u;
    unsigned sel = 0;
    int   out_e = 0;
    float out_w = 0.0f;

#pragma unroll
    for (int r = 0; r < TOP_K; r++) {
        float v = -INFINITY; int ie = N_EXPERTS;
        if (gok) {
#pragma unroll
            for (int j = 0; j < 8; j++) {
                if (!((sel >> j) & 1u)) {
                    int e = lane * 8 + j;
                    float val = s[e] + bs[e];
                    if (val > v) { v = val; ie = e; }
                }
            }
        }
        argmax_red(v, ie);
        if ((ie >> 3) == lane) sel |= 1u << (ie & 7);
        if (lane == r) { out_e = ie; out_w = s[ie]; }
    }

    float wsum = (lane < TOP_K) ? out_w : 0.0f;
#pragma unroll
    for (int o = 16; o > 0; o >>= 1)
        wsum += __shfl_down_sync(0xffffffffu, wsum, o);
    wsum = __shfl_sync(0xffffffffu, wsum, 0);

    if (lane < TOP_K) {
        float denom = wsum + 1e-20f;
        float wn = out_w / denom * 2.5f;
        if (out_size >= 2 * T * TOP_K) {
            out[(size_t)t * TOP_K + lane] = (float)out_e;
            out[(size_t)T * TOP_K + (size_t)t * TOP_K + lane] = wn;
        } else {
            out[(size_t)t * TOP_K + lane] = wn;
        }
    }
}

// ---------------------------------------------------------------------------
extern "C" void kernel_launch(void* const* d_in, const int* in_sizes, int n_in,
                              void* d_out, int out_size)
{
    const float* hidden = (const float*)d_in[0];
    const float* weight = (const float*)d_in[1];
    const float* bias   = (const float*)d_in[2];
    float* out = (float*)d_out;

    const int H = in_sizes[1] / N_EXPERTS;   // 7168
    const int T = in_sizes[0] / H;           // 8192

    static bool attr_set = false;
    if (!attr_set) {
        cudaFuncSetAttribute(gemm_mma_kernel,
                             cudaFuncAttributeMaxDynamicSharedMemorySize,
                             DSMEM_REQ);
        attr_set = true;
    }

    dim3 ggrid(N_EXPERTS / BN, (T + BM - 1) / BM);   // (2, 64)
    gemm_mma_kernel<<<ggrid, 512, DSMEM_REQ>>>(hidden, weight, T);

    int nblk = (T + 7) / 8;
    gate_kernel<<<nblk, 256>>>(bias, out, T, out_size);
}

// round 6
// speedup vs baseline: 2.7682x; 1.1938x over previous
#include <cuda_runtime.h>
#include <cuda_fp16.h>
#include <math.h>
#include <stdint.h>

// ============================================================================
// MoEGate (DeepSeek-V3 router) for GB300 — round 6
//   logits[T,256] = hidden[T,7168] @ weight[256,7168]^T
//   GEMM: mma.sync fp16 split (hi/lo, 3 products), fp32 two-level accumulation,
//   weights scaled x512 (residuals avoid fp16 denormals), unscale in epilogue.
//   Round-6 fixes: RSTRIDE 72->80 (conflict-free fragment LDS), fused uint4
//   STS.128 stores, packed f32x2->f16x2 conversion.
// Output (float32): [ topk_idx (T*8) ; topk_weight (T*8) ]
// ============================================================================

#define N_EXPERTS 256
#define N_GROUP 8
#define EPG 32
#define TOP_K 8
#define TOPK_GROUP 4
#define MAX_T 8192
#define KDIM 7168

#define WSCALE 512.0f
#define WUNSCALE 0.001953125f   // 1/512, exact

__device__ float g_logits[MAX_T * N_EXPERTS];

// ---------------------------------------------------------------------------
// GEMM: BM=128 x BN=128 per CTA, KC=32 fp32 per chunk, 16 warps (512 thr),
// warp tile 32x32 (4x4 warp grid).
// RSTRIDE=80B (20 words): lane word = lg*20+tg mod 32 is a permutation ->
// conflict-free fragment LDS.
// ---------------------------------------------------------------------------
#define BM 128
#define BN 128
#define KC 32
#define NCHUNK (KDIM / KC)          // 224
#define RSTRIDE 80                  // bytes per smem row (64B data + 16B pad)
#define TILE_B (128 * RSTRIDE)      // 10240 B
#define STAGE_B (4 * TILE_B)        // 40960 B
#define DSMEM_REQ (2 * STAGE_B)     // 81920 B

__device__ __forceinline__ void mma_f16(float* c, const uint32_t* a,
                                        const uint32_t* b) {
    asm volatile(
        "mma.sync.aligned.m16n8k16.row.col.f32.f16.f16.f32 "
        "{%0,%1,%2,%3}, {%4,%5,%6,%7}, {%8,%9}, {%0,%1,%2,%3};"
        : "+f"(c[0]), "+f"(c[1]), "+f"(c[2]), "+f"(c[3])
        : "r"(a[0]), "r"(a[1]), "r"(a[2]), "r"(a[3]), "r"(b[0]), "r"(b[1]));
}

__device__ __forceinline__ uint32_t pack2_hi(float x, float y) {
    __half2 h = __float22half2_rn(make_float2(x, y));
    return *(uint32_t*)&h;
}
__device__ __forceinline__ uint32_t pack2_lo(float x, float y) {
    __half2 h = __float22half2_rn(make_float2(x, y));
    float2 hf = __half22float2(h);
    __half2 l = __float22half2_rn(make_float2(x - hf.x, y - hf.y));
    return *(uint32_t*)&l;
}

// convert two k-adjacent float4 into hi/lo uint4 and store (STS.128 each)
__device__ __forceinline__ void cvt_store2(char* hi, char* lo, uint32_t off,
                                           float4 v0, float4 v1) {
    uint4 h = make_uint4(pack2_hi(v0.x, v0.y), pack2_hi(v0.z, v0.w),
                         pack2_hi(v1.x, v1.y), pack2_hi(v1.z, v1.w));
    uint4 l = make_uint4(pack2_lo(v0.x, v0.y), pack2_lo(v0.z, v0.w),
                         pack2_lo(v1.x, v1.y), pack2_lo(v1.z, v1.w));
    *(uint4*)(hi + off) = h;
    *(uint4*)(lo + off) = l;
}

__global__ void __launch_bounds__(512, 1)
gemm_mma_kernel(const float* __restrict__ A, const float* __restrict__ B, int T)
{
    extern __shared__ char smem[];

    const int tid  = threadIdx.x;
    const int wid  = tid >> 5;
    const int lane = tid & 31;
    const int bn = blockIdx.x * BN;
    const int bm = blockIdx.y * BM;

    const int wm = wid >> 2;           // 0..3 -> row offset 32*wm
    const int wn = wid & 3;            // 0..3 -> col offset 32*wn
    const int lg = lane >> 2;          // 0..7
    const int tg = lane & 3;           // 0..3

    // loader: row = tid>>2 (0..127), quarter q = tid&3 -> k offset q*8 floats
    const int lrow = tid >> 2;
    const int lq   = tid & 3;
    const float* Ag = A + (size_t)(bm + lrow) * KDIM + lq * 8;
    const float* Bg = B + (size_t)(bn + lrow) * KDIM + lq * 8;
    const uint32_t sto = (uint32_t)(lrow * RSTRIDE + lq * 16);  // fp16 bytes

    float accH[2][4][4], accL[2][4][4];
#pragma unroll
    for (int i = 0; i < 2; i++)
#pragma unroll
        for (int j = 0; j < 4; j++)
#pragma unroll
            for (int q = 0; q < 4; q++) { accH[i][j][q] = 0.0f; accL[i][j][q] = 0.0f; }

    // ---- prologue: chunk 0 -> stage 0 ----
    {
        float4 a0 = *(const float4*)(Ag);
        float4 a1 = *(const float4*)(Ag + 4);
        float4 b0 = *(const float4*)(Bg);
        float4 b1 = *(const float4*)(Bg + 4);
        b0.x *= WSCALE; b0.y *= WSCALE; b0.z *= WSCALE; b0.w *= WSCALE;
        b1.x *= WSCALE; b1.y *= WSCALE; b1.z *= WSCALE; b1.w *= WSCALE;
        cvt_store2(smem,              smem + TILE_B,     sto, a0, a1);
        cvt_store2(smem + 2 * TILE_B, smem + 3 * TILE_B, sto, b0, b1);
    }
    __syncthreads();

    for (int i = 0; i < NCHUNK; i++) {
        const int b = i & 1;
        char* st = smem + b * STAGE_B;
        char* sAhi = st;               char* sAlo = st + TILE_B;
        char* sBhi = st + 2 * TILE_B;  char* sBlo = st + 3 * TILE_B;

        // prefetch next chunk into registers
        float4 ar0, ar1, br0, br1;
        const bool more = (i + 1 < NCHUNK);
        if (more) {
            const size_t k0 = (size_t)(i + 1) * KC;
            ar0 = *(const float4*)(Ag + k0);
            ar1 = *(const float4*)(Ag + k0 + 4);
            br0 = *(const float4*)(Bg + k0);
            br1 = *(const float4*)(Bg + k0 + 4);
        }

        // compute: 2 k-steps x 3 products x 8 mma
#pragma unroll
        for (int ks = 0; ks < 2; ks++) {
            const uint32_t kb = ks * 32;
            uint32_t afr[2][4], bhi[4][2], blo[4][2];

#pragma unroll
            for (int mt = 0; mt < 2; mt++) {
                uint32_t o = (uint32_t)((wm * 32 + mt * 16 + lg) * RSTRIDE) + kb + tg * 4;
                afr[mt][0] = *(const uint32_t*)(sAhi + o);
                afr[mt][1] = *(const uint32_t*)(sAhi + o + 8 * RSTRIDE);
                afr[mt][2] = *(const uint32_t*)(sAhi + o + 16);
                afr[mt][3] = *(const uint32_t*)(sAhi + o + 8 * RSTRIDE + 16);
            }
#pragma unroll
            for (int nt = 0; nt < 4; nt++) {
                uint32_t o = (uint32_t)((wn * 32 + nt * 8 + lg) * RSTRIDE) + kb + tg * 4;
                bhi[nt][0] = *(const uint32_t*)(sBhi + o);
                bhi[nt][1] = *(const uint32_t*)(sBhi + o + 16);
            }
#pragma unroll
            for (int mt = 0; mt < 2; mt++)
#pragma unroll
                for (int nt = 0; nt < 4; nt++)
                    mma_f16(accL[mt][nt], afr[mt], bhi[nt]);

#pragma unroll
            for (int nt = 0; nt < 4; nt++) {
                uint32_t o = (uint32_t)((wn * 32 + nt * 8 + lg) * RSTRIDE) + kb + tg * 4;
                blo[nt][0] = *(const uint32_t*)(sBlo + o);
                blo[nt][1] = *(const uint32_t*)(sBlo + o + 16);
            }
#pragma unroll
            for (int mt = 0; mt < 2; mt++)
#pragma unroll
                for (int nt = 0; nt < 4; nt++)
                    mma_f16(accL[mt][nt], afr[mt], blo[nt]);

#pragma unroll
            for (int mt = 0; mt < 2; mt++) {
                uint32_t o = (uint32_t)((wm * 32 + mt * 16 + lg) * RSTRIDE) + kb + tg * 4;
                afr[mt][0] = *(const uint32_t*)(sAlo + o);
                afr[mt][1] = *(const uint32_t*)(sAlo + o + 8 * RSTRIDE);
                afr[mt][2] = *(const uint32_t*)(sAlo + o + 16);
                afr[mt][3] = *(const uint32_t*)(sAlo + o + 8 * RSTRIDE + 16);
            }
#pragma unroll
            for (int mt = 0; mt < 2; mt++)
#pragma unroll
                for (int nt = 0; nt < 4; nt++)
                    mma_f16(accL[mt][nt], afr[mt], bhi[nt]);
        }

        // fold local -> main every 8 chunks (224 % 8 == 0)
        if ((i & 7) == 7) {
#pragma unroll
            for (int mt = 0; mt < 2; mt++)
#pragma unroll
                for (int nt = 0; nt < 4; nt++)
#pragma unroll
                    for (int q = 0; q < 4; q++) {
                        accH[mt][nt][q] += accL[mt][nt][q];
                        accL[mt][nt][q] = 0.0f;
                    }
        }

        // convert + store next chunk into other stage
        if (more) {
            char* nst = smem + (b ^ 1) * STAGE_B;
            br0.x *= WSCALE; br0.y *= WSCALE; br0.z *= WSCALE; br0.w *= WSCALE;
            br1.x *= WSCALE; br1.y *= WSCALE; br1.z *= WSCALE; br1.w *= WSCALE;
            cvt_store2(nst,              nst + TILE_B,     sto, ar0, ar1);
            cvt_store2(nst + 2 * TILE_B, nst + 3 * TILE_B, sto, br0, br1);
        }
        __syncthreads();
    }

    // ---- epilogue: unscale by 1/512 and write logits ----
#pragma unroll
    for (int mt = 0; mt < 2; mt++) {
#pragma unroll
        for (int nt = 0; nt < 4; nt++) {
            int row0 = bm + wm * 32 + mt * 16 + lg;
            int col  = bn + wn * 32 + nt * 8 + tg * 2;
            float* d0 = g_logits + (size_t)row0 * N_EXPERTS + col;
            float* d1 = g_logits + (size_t)(row0 + 8) * N_EXPERTS + col;
            *(float2*)d0 = make_float2(accH[mt][nt][0] * WUNSCALE,
                                       accH[mt][nt][1] * WUNSCALE);
            *(float2*)d1 = make_float2(accH[mt][nt][2] * WUNSCALE,
                                       accH[mt][nt][3] * WUNSCALE);
        }
    }
}

// ---------------------------------------------------------------------------
// Gating: one warp per token (verified correct).
// ---------------------------------------------------------------------------
__device__ __forceinline__ void argmax_red(float& v, int& i)
{
#pragma unroll
    for (int o = 16; o > 0; o >>= 1) {
        float v2 = __shfl_down_sync(0xffffffffu, v, o);
        int   i2 = __shfl_down_sync(0xffffffffu, i, o);
        if (v2 > v || (v2 == v && i2 < i)) { v = v2; i = i2; }
    }
    v = __shfl_sync(0xffffffffu, v, 0);
    i = __shfl_sync(0xffffffffu, i, 0);
}

__global__ void __launch_bounds__(256)
gate_kernel(const float* __restrict__ bias, float* __restrict__ out,
            int T, int out_size)
{
    __shared__ float ss[8][N_EXPERTS];
    __shared__ float bs[N_EXPERTS];

    const int tid  = threadIdx.x;
    const int warp = tid >> 5;
    const int lane = tid & 31;
    const int t = blockIdx.x * 8 + warp;

    if (tid < N_EXPERTS) bs[tid] = bias[tid];

    float* s = ss[warp];
    if (t < T) {
        const float* lg = g_logits + (size_t)t * N_EXPERTS;
#pragma unroll
        for (int j = 0; j < 8; j++) {
            int e = j * 32 + lane;
            float x = lg[e];
            s[e] = 1.0f / (1.0f + expf(-x));
        }
    }
    __syncthreads();
    if (t >= T) return;

    float gsum_mine = 0.0f;
#pragma unroll
    for (int g = 0; g < N_GROUP; g++) {
        int e = g * EPG + lane;
        float v = s[e] + bs[e];
        float v1 = v; int i1 = lane;
        argmax_red(v1, i1);
        float v2 = (lane == i1) ? -INFINITY : v;
        int   i2 = lane;
        argmax_red(v2, i2);
        if (lane == g) gsum_mine = v1 + v2;
    }

    float gv[N_GROUP];
#pragma unroll
    for (int j = 0; j < N_GROUP; j++)
        gv[j] = __shfl_sync(0xffffffffu, gsum_mine, j);

    unsigned gmask = 0;
#pragma unroll
    for (int r = 0; r < TOPK_GROUP; r++) {
        float best = -INFINITY; int bi = 0;
#pragma unroll
        for (int j = 0; j < N_GROUP; j++) {
            if (!((gmask >> j) & 1u) && gv[j] > best) { best = gv[j]; bi = j; }
        }
        gmask |= 1u << bi;
    }

    const bool gok = (gmask >> (lane >> 2)) & 1u;
    unsigned sel = 0;
    int   out_e = 0;
    float out_w = 0.0f;

#pragma unroll
    for (int r = 0; r < TOP_K; r++) {
        float v = -INFINITY; int ie = N_EXPERTS;
        if (gok) {
#pragma unroll
            for (int j = 0; j < 8; j++) {
                if (!((sel >> j) & 1u)) {
                    int e = lane * 8 + j;
                    float val = s[e] + bs[e];
                    if (val > v) { v = val; ie = e; }
                }
            }
        }
        argmax_red(v, ie);
        if ((ie >> 3) == lane) sel |= 1u << (ie & 7);
        if (lane == r) { out_e = ie; out_w = s[ie]; }
    }

    float wsum = (lane < TOP_K) ? out_w : 0.0f;
#pragma unroll
    for (int o = 16; o > 0; o >>= 1)
        wsum += __shfl_down_sync(0xffffffffu, wsum, o);
    wsum = __shfl_sync(0xffffffffu, wsum, 0);

    if (lane < TOP_K) {
        float denom = wsum + 1e-20f;
        float wn = out_w / denom * 2.5f;
        if (out_size >= 2 * T * TOP_K) {
            out[(size_t)t * TOP_K + lane] = (float)out_e;
            out[(size_t)T * TOP_K + (size_t)t * TOP_K + lane] = wn;
        } else {
            out[(size_t)t * TOP_K + lane] = wn;
        }
    }
}

// ---------------------------------------------------------------------------
extern "C" void kernel_launch(void* const* d_in, const int* in_sizes, int n_in,
                              void* d_out, int out_size)
{
    const float* hidden = (const float*)d_in[0];
    const float* weight = (const float*)d_in[1];
    const float* bias   = (const float*)d_in[2];
    float* out = (float*)d_out;

    const int H = in_sizes[1] / N_EXPERTS;   // 7168
    const int T = in_sizes[0] / H;           // 8192

    static bool attr_set = false;
    if (!attr_set) {
        cudaFuncSetAttribute(gemm_mma_kernel,
                             cudaFuncAttributeMaxDynamicSharedMemorySize,
                             DSMEM_REQ);
        attr_set = true;
    }

    dim3 ggrid(N_EXPERTS / BN, (T + BM - 1) / BM);   // (2, 64)
    gemm_mma_kernel<<<ggrid, 512, DSMEM_REQ>>>(hidden, weight, T);

    int nblk = (T + 7) / 8;
    gate_kernel<<<nblk, 256>>>(bias, out, T, out_size);
}

// round 7
// speedup vs baseline: 3.0777x; 1.1118x over previous
#include <cuda_runtime.h>
#include <cuda_fp16.h>
#include <math.h>
#include <stdint.h>

// ============================================================================
// MoEGate (DeepSeek-V3 router) for GB300 — round 7
//   logits[T,256] = hidden[T,7168] @ weight[256,7168]^T
//   GEMM: mma.sync fp16 split (hi/lo, 3 products), fp32 two-level accumulation,
//   weights scaled x512, unscale in epilogue.
//   Round-7: ldmatrix.x4 fragment loads (32 LDS.32 -> 8 LDSM.x4 per warp/ks).
// Output (float32): [ topk_idx (T*8) ; topk_weight (T*8) ]
// ============================================================================

#define N_EXPERTS 256
#define N_GROUP 8
#define EPG 32
#define TOP_K 8
#define TOPK_GROUP 4
#define MAX_T 8192
#define KDIM 7168

#define WSCALE 512.0f
#define WUNSCALE 0.001953125f   // 1/512, exact

__device__ float g_logits[MAX_T * N_EXPERTS];

#define BM 128
#define BN 128
#define KC 32
#define NCHUNK (KDIM / KC)          // 224
#define RSTRIDE 80                  // bytes per smem row (64B data + 16B pad)
#define TILE_B (128 * RSTRIDE)      // 10240 B
#define STAGE_B (4 * TILE_B)        // 40960 B
#define DSMEM_REQ (2 * STAGE_B)     // 81920 B

__device__ __forceinline__ uint32_t smem_u32(const void* p) {
    uint32_t a;
    asm("{ .reg .u64 t; cvta.to.shared.u64 t, %1; cvt.u32.u64 %0, t; }"
        : "=r"(a) : "l"(p));
    return a;
}

#define LDSM_X4(r0, r1, r2, r3, addr)                                          \
    asm volatile("ldmatrix.sync.aligned.m8n8.x4.shared.b16 {%0,%1,%2,%3}, [%4];" \
        : "=r"(r0), "=r"(r1), "=r"(r2), "=r"(r3) : "r"(addr))

__device__ __forceinline__ void mma_f16(float* c, const uint32_t* a,
                                        const uint32_t* b) {
    asm volatile(
        "mma.sync.aligned.m16n8k16.row.col.f32.f16.f16.f32 "
        "{%0,%1,%2,%3}, {%4,%5,%6,%7}, {%8,%9}, {%0,%1,%2,%3};"
        : "+f"(c[0]), "+f"(c[1]), "+f"(c[2]), "+f"(c[3])
        : "r"(a[0]), "r"(a[1]), "r"(a[2]), "r"(a[3]), "r"(b[0]), "r"(b[1]));
}

__device__ __forceinline__ uint32_t pack2_hi(float x, float y) {
    __half2 h = __float22half2_rn(make_float2(x, y));
    return *(uint32_t*)&h;
}
__device__ __forceinline__ uint32_t pack2_lo(float x, float y) {
    __half2 h = __float22half2_rn(make_float2(x, y));
    float2 hf = __half22float2(h);
    __half2 l = __float22half2_rn(make_float2(x - hf.x, y - hf.y));
    return *(uint32_t*)&l;
}

__device__ __forceinline__ void cvt_store2(char* hi, char* lo, uint32_t off,
                                           float4 v0, float4 v1) {
    uint4 h = make_uint4(pack2_hi(v0.x, v0.y), pack2_hi(v0.z, v0.w),
                         pack2_hi(v1.x, v1.y), pack2_hi(v1.z, v1.w));
    uint4 l = make_uint4(pack2_lo(v0.x, v0.y), pack2_lo(v0.z, v0.w),
                         pack2_lo(v1.x, v1.y), pack2_lo(v1.z, v1.w));
    *(uint4*)(hi + off) = h;
    *(uint4*)(lo + off) = l;
}

__global__ void __launch_bounds__(512, 1)
gemm_mma_kernel(const float* __restrict__ A, const float* __restrict__ B, int T)
{
    extern __shared__ char smem[];
    const uint32_t sbase = smem_u32(smem);

    const int tid  = threadIdx.x;
    const int wid  = tid >> 5;
    const int lane = tid & 31;
    const int bn = blockIdx.x * BN;
    const int bm = blockIdx.y * BM;

    const int wm = wid >> 2;           // 0..3 -> row offset 32*wm
    const int wn = wid & 3;            // 0..3 -> col offset 32*wn

    // ldmatrix per-lane addressing: row = lane%16, k-half = (lane>>4)*8 halves
    const uint32_t lrow16 = (uint32_t)(lane & 15);
    const uint32_t lkoff  = (uint32_t)((lane >> 4) * 16);  // bytes
    const uint32_t aRow = (uint32_t)(wm * 32 + lrow16) * RSTRIDE + lkoff;
    const uint32_t bRow = (uint32_t)(wn * 32 + lrow16) * RSTRIDE + lkoff;

    // loader: row = tid>>2 (0..127), quarter q = tid&3 -> k offset q*8 floats
    const int lrowL = tid >> 2;
    const int lq    = tid & 3;
    const float* Ag = A + (size_t)(bm + lrowL) * KDIM + lq * 8;
    const float* Bg = B + (size_t)(bn + lrowL) * KDIM + lq * 8;
    const uint32_t sto = (uint32_t)(lrowL * RSTRIDE + lq * 16);

    float accH[2][4][4], accL[2][4][4];
#pragma unroll
    for (int i = 0; i < 2; i++)
#pragma unroll
        for (int j = 0; j < 4; j++)
#pragma unroll
            for (int q = 0; q < 4; q++) { accH[i][j][q] = 0.0f; accL[i][j][q] = 0.0f; }

    // ---- prologue: chunk 0 -> stage 0 ----
    {
        float4 a0 = *(const float4*)(Ag);
        float4 a1 = *(const float4*)(Ag + 4);
        float4 b0 = *(const float4*)(Bg);
        float4 b1 = *(const float4*)(Bg + 4);
        b0.x *= WSCALE; b0.y *= WSCALE; b0.z *= WSCALE; b0.w *= WSCALE;
        b1.x *= WSCALE; b1.y *= WSCALE; b1.z *= WSCALE; b1.w *= WSCALE;
        cvt_store2(smem,              smem + TILE_B,     sto, a0, a1);
        cvt_store2(smem + 2 * TILE_B, smem + 3 * TILE_B, sto, b0, b1);
    }
    __syncthreads();

    for (int i = 0; i < NCHUNK; i++) {
        const int b = i & 1;
        const uint32_t st = sbase + (uint32_t)b * STAGE_B;
        const uint32_t sAhi = st;
        const uint32_t sAlo = st + TILE_B;
        const uint32_t sBhi = st + 2 * TILE_B;
        const uint32_t sBlo = st + 3 * TILE_B;

        // prefetch next chunk into registers
        float4 ar0, ar1, br0, br1;
        const bool more = (i + 1 < NCHUNK);
        if (more) {
            const size_t k0 = (size_t)(i + 1) * KC;
            ar0 = *(const float4*)(Ag + k0);
            ar1 = *(const float4*)(Ag + k0 + 4);
            br0 = *(const float4*)(Bg + k0);
            br1 = *(const float4*)(Bg + k0 + 4);
        }

        // compute: 2 k-steps x 3 products x 8 mma; fragments via ldmatrix.x4
#pragma unroll
        for (int ks = 0; ks < 2; ks++) {
            const uint32_t kb = ks * 32;
            uint32_t afr[2][4], bhi[4][2], blo[4][2];

            // A-hi: 2 x (m16 x k16) tiles
#pragma unroll
            for (int mt = 0; mt < 2; mt++)
                LDSM_X4(afr[mt][0], afr[mt][1], afr[mt][2], afr[mt][3],
                        sAhi + aRow + (uint32_t)(mt * 16) * RSTRIDE + kb);
            // B-hi: 2 x (n16 x k16) tiles -> 4 n8 fragments
#pragma unroll
            for (int p = 0; p < 2; p++) {
                uint32_t t0, t1, t2, t3;
                LDSM_X4(t0, t1, t2, t3,
                        sBhi + bRow + (uint32_t)(p * 16) * RSTRIDE + kb);
                bhi[2*p][0] = t0;   bhi[2*p][1] = t2;
                bhi[2*p+1][0] = t1; bhi[2*p+1][1] = t3;
            }
#pragma unroll
            for (int mt = 0; mt < 2; mt++)
#pragma unroll
                for (int nt = 0; nt < 4; nt++)
                    mma_f16(accL[mt][nt], afr[mt], bhi[nt]);

            // B-lo
#pragma unroll
            for (int p = 0; p < 2; p++) {
                uint32_t t0, t1, t2, t3;
                LDSM_X4(t0, t1, t2, t3,
                        sBlo + bRow + (uint32_t)(p * 16) * RSTRIDE + kb);
                blo[2*p][0] = t0;   blo[2*p][1] = t2;
                blo[2*p+1][0] = t1; blo[2*p+1][1] = t3;
            }
#pragma unroll
            for (int mt = 0; mt < 2; mt++)
#pragma unroll
                for (int nt = 0; nt < 4; nt++)
                    mma_f16(accL[mt][nt], afr[mt], blo[nt]);

            // A-lo (reuse afr regs)
#pragma unroll
            for (int mt = 0; mt < 2; mt++)
                LDSM_X4(afr[mt][0], afr[mt][1], afr[mt][2], afr[mt][3],
                        sAlo + aRow + (uint32_t)(mt * 16) * RSTRIDE + kb);
#pragma unroll
            for (int mt = 0; mt < 2; mt++)
#pragma unroll
                for (int nt = 0; nt < 4; nt++)
                    mma_f16(accL[mt][nt], afr[mt], bhi[nt]);
        }

        // fold local -> main every 8 chunks (224 % 8 == 0)
        if ((i & 7) == 7) {
#pragma unroll
            for (int mt = 0; mt < 2; mt++)
#pragma unroll
                for (int nt = 0; nt < 4; nt++)
#pragma unroll
                    for (int q = 0; q < 4; q++) {
                        accH[mt][nt][q] += accL[mt][nt][q];
                        accL[mt][nt][q] = 0.0f;
                    }
        }

        // convert + store next chunk into other stage
        if (more) {
            char* nst = smem + (b ^ 1) * STAGE_B;
            br0.x *= WSCALE; br0.y *= WSCALE; br0.z *= WSCALE; br0.w *= WSCALE;
            br1.x *= WSCALE; br1.y *= WSCALE; br1.z *= WSCALE; br1.w *= WSCALE;
            cvt_store2(nst,              nst + TILE_B,     sto, ar0, ar1);
            cvt_store2(nst + 2 * TILE_B, nst + 3 * TILE_B, sto, br0, br1);
        }
        __syncthreads();
    }

    // ---- epilogue: unscale by 1/512 and write logits ----
    const int lg = lane >> 2;
    const int tg = lane & 3;
#pragma unroll
    for (int mt = 0; mt < 2; mt++) {
#pragma unroll
        for (int nt = 0; nt < 4; nt++) {
            int row0 = bm + wm * 32 + mt * 16 + lg;
            int col  = bn + wn * 32 + nt * 8 + tg * 2;
            float* d0 = g_logits + (size_t)row0 * N_EXPERTS + col;
            float* d1 = g_logits + (size_t)(row0 + 8) * N_EXPERTS + col;
            *(float2*)d0 = make_float2(accH[mt][nt][0] * WUNSCALE,
                                       accH[mt][nt][1] * WUNSCALE);
            *(float2*)d1 = make_float2(accH[mt][nt][2] * WUNSCALE,
                                       accH[mt][nt][3] * WUNSCALE);
        }
    }
}

// ---------------------------------------------------------------------------
// Gating: one warp per token (verified correct).
// ---------------------------------------------------------------------------
__device__ __forceinline__ void argmax_red(float& v, int& i)
{
#pragma unroll
    for (int o = 16; o > 0; o >>= 1) {
        float v2 = __shfl_down_sync(0xffffffffu, v, o);
        int   i2 = __shfl_down_sync(0xffffffffu, i, o);
        if (v2 > v || (v2 == v && i2 < i)) { v = v2; i = i2; }
    }
    v = __shfl_sync(0xffffffffu, v, 0);
    i = __shfl_sync(0xffffffffu, i, 0);
}

__global__ void __launch_bounds__(256)
gate_kernel(const float* __restrict__ bias, float* __restrict__ out,
            int T, int out_size)
{
    __shared__ float ss[8][N_EXPERTS];
    __shared__ float bs[N_EXPERTS];

    const int tid  = threadIdx.x;
    const int warp = tid >> 5;
    const int lane = tid & 31;
    const int t = blockIdx.x * 8 + warp;

    if (tid < N_EXPERTS) bs[tid] = bias[tid];

    float* s = ss[warp];
    if (t < T) {
        const float* lg = g_logits + (size_t)t * N_EXPERTS;
#pragma unroll
        for (int j = 0; j < 8; j++) {
            int e = j * 32 + lane;
            float x = lg[e];
            s[e] = 1.0f / (1.0f + expf(-x));
        }
    }
    __syncthreads();
    if (t >= T) return;

    float gsum_mine = 0.0f;
#pragma unroll
    for (int g = 0; g < N_GROUP; g++) {
        int e = g * EPG + lane;
        float v = s[e] + bs[e];
        float v1 = v; int i1 = lane;
        argmax_red(v1, i1);
        float v2 = (lane == i1) ? -INFINITY : v;
        int   i2 = lane;
        argmax_red(v2, i2);
        if (lane == g) gsum_mine = v1 + v2;
    }

    float gv[N_GROUP];
#pragma unroll
    for (int j = 0; j < N_GROUP; j++)
        gv[j] = __shfl_sync(0xffffffffu, gsum_mine, j);

    unsigned gmask = 0;
#pragma unroll
    for (int r = 0; r < TOPK_GROUP; r++) {
        float best = -INFINITY; int bi = 0;
#pragma unroll
        for (int j = 0; j < N_GROUP; j++) {
            if (!((gmask >> j) & 1u) && gv[j] > best) { best = gv[j]; bi = j; }
        }
        gmask |= 1u << bi;
    }

    const bool gok = (gmask >> (lane >> 2)) & 1u;
    unsigned sel = 0;
    int   out_e = 0;
    float out_w = 0.0f;

#pragma unroll
    for (int r = 0; r < TOP_K; r++) {
        float v = -INFINITY; int ie = N_EXPERTS;
        if (gok) {
#pragma unroll
            for (int j = 0; j < 8; j++) {
                if (!((sel >> j) & 1u)) {
                    int e = lane * 8 + j;
                    float val = s[e] + bs[e];
                    if (val > v) { v = val; ie = e; }
                }
            }
        }
        argmax_red(v, ie);
        if ((ie >> 3) == lane) sel |= 1u << (ie & 7);
        if (lane == r) { out_e = ie; out_w = s[ie]; }
    }

    float wsum = (lane < TOP_K) ? out_w : 0.0f;
#pragma unroll
    for (int o = 16; o > 0; o >>= 1)
        wsum += __shfl_down_sync(0xffffffffu, wsum, o);
    wsum = __shfl_sync(0xffffffffu, wsum, 0);

    if (lane < TOP_K) {
        float denom = wsum + 1e-20f;
        float wn = out_w / denom * 2.5f;
        if (out_size >= 2 * T * TOP_K) {
            out[(size_t)t * TOP_K + lane] = (float)out_e;
            out[(size_t)T * TOP_K + (size_t)t * TOP_K + lane] = wn;
        } else {
            out[(size_t)t * TOP_K + lane] = wn;
        }
    }
}

// ---------------------------------------------------------------------------
extern "C" void kernel_launch(void* const* d_in, const int* in_sizes, int n_in,
                              void* d_out, int out_size)
{
    const float* hidden = (const float*)d_in[0];
    const float* weight = (const float*)d_in[1];
    const float* bias   = (const float*)d_in[2];
    float* out = (float*)d_out;

    const int H = in_sizes[1] / N_EXPERTS;   // 7168
    const int T = in_sizes[0] / H;           // 8192

    static bool attr_set = false;
    if (!attr_set) {
        cudaFuncSetAttribute(gemm_mma_kernel,
                             cudaFuncAttributeMaxDynamicSharedMemorySize,
                             DSMEM_REQ);
        attr_set = true;
    }

    dim3 ggrid(N_EXPERTS / BN, (T + BM - 1) / BM);   // (2, 64)
    gemm_mma_kernel<<<ggrid, 512, DSMEM_REQ>>>(hidden, weight, T);

    int nblk = (T + 7) / 8;
    gate_kernel<<<nblk, 256>>>(bias, out, T, out_size);
}